// round 10
// baseline (speedup 1.0000x reference)
#include <cuda_runtime.h>
#include <cuda.h>
#include <cuda_bf16.h>
#include <cstdint>

#define HID 128
#define BM 128
#define TILE_BYTES 65536
#define GRID 148
#define NTHREADS 256

// ---- smem map ----
// prologue: P0 @0, P1 @67584, P2 @135168   (each padded [128][132] fp32 = 67584B)
// main:     XS0 @0, XS1 @65536, XS2 @131072 (64KB fp32 SW128 each), XB @196608 (32KB)
// mbar @229376 (24B); aux: u @229440, w @229952, c @230464 (512B each)
#define OFF_XB   196608u
#define OFF_MBAR 229376u
#define OFF_U    229440u
#define OFF_W    229952u
#define OFF_C    230464u
#define SMEM_TOTAL 230976
#define OFF_P0   0u
#define OFF_P1   67584u
#define OFF_P2   135168u
#define PSTR     132

__device__ __forceinline__ uint32_t smem_u32(const void* p) {
    uint32_t a;
    asm("{ .reg .u64 t; cvta.to.shared.u64 t, %1; cvt.u32.u64 %0, t; }" : "=r"(a) : "l"(p));
    return a;
}
__device__ __forceinline__ float warp_red(float p) {
    p += __shfl_xor_sync(0xffffffffu, p, 16);
    p += __shfl_xor_sync(0xffffffffu, p, 8);
    p += __shfl_xor_sync(0xffffffffu, p, 4);
    p += __shfl_xor_sync(0xffffffffu, p, 2);
    p += __shfl_xor_sync(0xffffffffu, p, 1);
    return p;
}
__device__ __forceinline__ uint32_t f2tf32(float x) {
    uint32_t r;
    asm("cvt.rna.tf32.f32 %0, %1;" : "=r"(r) : "f"(x));
    return r;
}
__device__ __forceinline__ float lds_f32(uint32_t a) {
    float f;
    asm volatile("ld.shared.f32 %0, [%1];" : "=f"(f) : "r"(a));
    return f;
}
__device__ __forceinline__ uint32_t packbf(float lo, float hi) {
    uint32_t d;
    asm("cvt.rn.bf16x2.f32 %0, %1, %2;" : "=r"(d) : "f"(hi), "f"(lo));
    return d;
}

#define CPA16(dst, src) \
    asm volatile("cp.async.cg.shared.global [%0], [%1], 16;" :: "r"(dst), "l"(src))
#define CPA_WAIT_ALL() \
    asm volatile("cp.async.commit_group;\ncp.async.wait_group 0;" ::: "memory")

#define MBAR_INIT(a, c) \
    asm volatile("mbarrier.init.shared.b64 [%0], %1;" :: "r"(a), "r"(c) : "memory")
#define MBAR_EXPECT(a, b) \
    asm volatile("mbarrier.arrive.expect_tx.shared.b64 _, [%0], %1;" :: "r"(a), "r"(b) : "memory")
#define MBAR_WAIT(mbar, par) do {                                             \
    uint32_t _m = (mbar); uint32_t _p = (par); uint32_t _d;                   \
    asm volatile("{\n\t.reg .pred p;\n\t"                                     \
        "mbarrier.try_wait.parity.acquire.cta.shared::cta.b64 p, [%1], %2;\n\t" \
        "selp.b32 %0, 1, 0, p;\n\t}"                                          \
        : "=r"(_d) : "r"(_m), "r"(_p) : "memory");                            \
    if (!_d) {                                                                \
        asm volatile("{\n\t.reg .pred P1;\n\t"                                \
            "W_%=:\n\t"                                                       \
            "mbarrier.try_wait.parity.acquire.cta.shared::cta.b64 P1, [%0], %1, 0x989680;\n\t" \
            "@P1 bra.uni D_%=;\n\t"                                           \
            "bra.uni W_%=;\n\t"                                               \
            "D_%=:\n\t}" :: "r"(_m), "r"(_p) : "memory");                     \
    }                                                                         \
} while (0)

#define TMA_LOAD2D(dst, map, x, y, mb) \
    asm volatile("cp.async.bulk.tensor.2d.shared::cta.global.tile.mbarrier::complete_tx::bytes " \
                 "[%0], [%1, {%2, %3}], [%4];" \
                 :: "r"(dst), "l"(map), "r"(x), "r"(y), "r"(mb) : "memory")
#define TMA_STORE2D(map, x, y, src) \
    asm volatile("cp.async.bulk.tensor.2d.global.shared::cta.tile.bulk_group " \
                 "[%0, {%1, %2}], [%3];" \
                 :: "l"(map), "r"(x), "r"(y), "r"(src) : "memory")
#define FENCE_ASYNC() asm volatile("fence.proxy.async.shared::cta;" ::: "memory")

__global__ __launch_bounds__(NTHREADS, 1) void fused_all(
    const __grid_constant__ CUtensorMap tmX,
    const __grid_constant__ CUtensorMap tmY,
    const float* __restrict__ Wo, const float* __restrict__ W_mo,
    const float* __restrict__ W_in, const float* __restrict__ Wv,
    const float* __restrict__ bv, const float* __restrict__ b_in,
    const float* __restrict__ b_mo, const float* __restrict__ bo,
    int ntiles)
{
    extern __shared__ __align__(1024) unsigned char smem_raw[];
    const uint32_t sb = smem_u32(smem_raw);
    const int tid  = threadIdx.x;
    const int lane = tid & 31, wid = tid >> 5;
    const int wm = wid & 1, wn = wid >> 1;      // 2(m) x 4(n) warp grid
    const int lq = lane >> 2, lr = lane & 3;
    const int bid = blockIdx.x;

    const uint32_t p0 = sb + OFF_P0, p1 = sb + OFF_P1, p2 = sb + OFF_P2;
    const uint32_t xbB = sb + OFF_XB;
    const uint32_t auxU = sb + OFF_U, auxW = sb + OFF_W, auxC = sb + OFF_C;

    if (tid == 0) {
        MBAR_INIT(sb + OFF_MBAR + 0, 1);
        MBAR_INIT(sb + OFF_MBAR + 8, 1);
        MBAR_INIT(sb + OFF_MBAR + 16, 1);
    }
    __syncthreads();

    // ---- stage helper: 64KB row-major fp32 -> padded [128][132] ----
    auto stage64 = [&](uint32_t dst, const float* src) {
        #pragma unroll
        for (int qq = 0; qq < 16; ++qq) {
            const int i = qq * 256 + tid;          // 16B chunks
            const uint32_t row = (uint32_t)i >> 5;
            const uint32_t c16 = (uint32_t)i & 31;
            CPA16(dst + row * (PSTR * 4) + c16 * 16, src + i * 4);
        }
    };
    // ---- tf32 GEMM: acc += P(a) @ P(b), both padded [128][132] ----
    float acc[4][4][4];
    auto zero_acc = [&]() {
        #pragma unroll
        for (int mt = 0; mt < 4; ++mt)
            #pragma unroll
            for (int nt = 0; nt < 4; ++nt)
                #pragma unroll
                for (int q = 0; q < 4; ++q) acc[mt][nt][q] = 0.f;
    };
    auto gemm_tf32 = [&](uint32_t aB, uint32_t bB) {
        #pragma unroll
        for (int ks = 0; ks < 16; ++ks) {
            uint32_t a[4][4];
            #pragma unroll
            for (int mt = 0; mt < 4; ++mt) {
                const uint32_t r0 = (uint32_t)(wm * 64 + mt * 16 + lq);
                const uint32_t cA = (uint32_t)(ks * 8 + lr);
                a[mt][0] = f2tf32(lds_f32(aB + (r0 * PSTR + cA) * 4));
                a[mt][1] = f2tf32(lds_f32(aB + ((r0 + 8) * PSTR + cA) * 4));
                a[mt][2] = f2tf32(lds_f32(aB + (r0 * PSTR + cA + 4) * 4));
                a[mt][3] = f2tf32(lds_f32(aB + ((r0 + 8) * PSTR + cA + 4) * 4));
            }
            #pragma unroll
            for (int nt = 0; nt < 4; ++nt) {
                const uint32_t cn = (uint32_t)(wn * 32 + nt * 8 + lq);
                const uint32_t b0 = f2tf32(lds_f32(bB + ((ks * 8 + lr) * PSTR + cn) * 4));
                const uint32_t b1 = f2tf32(lds_f32(bB + ((ks * 8 + lr + 4) * PSTR + cn) * 4));
                #pragma unroll
                for (int mt = 0; mt < 4; ++mt) {
                    asm volatile(
                        "mma.sync.aligned.m16n8k8.row.col.f32.tf32.tf32.f32 "
                        "{%0,%1,%2,%3}, {%4,%5,%6,%7}, {%8,%9}, {%0,%1,%2,%3};"
                        : "+f"(acc[mt][nt][0]), "+f"(acc[mt][nt][1]),
                          "+f"(acc[mt][nt][2]), "+f"(acc[mt][nt][3])
                        : "r"(a[mt][0]), "r"(a[mt][1]), "r"(a[mt][2]), "r"(a[mt][3]),
                          "r"(b0), "r"(b1));
                }
            }
        }
    };
    auto store_acc = [&](uint32_t base) {
        #pragma unroll
        for (int mt = 0; mt < 4; ++mt) {
            const uint32_t r0 = (uint32_t)(wm * 64 + mt * 16 + lq);
            #pragma unroll
            for (int nt = 0; nt < 4; ++nt) {
                const uint32_t col = (uint32_t)(wn * 32 + nt * 8 + 2 * lr);
                asm volatile("st.shared.v2.f32 [%0], {%1,%2};"
                             :: "r"(base + (r0 * PSTR + col) * 4),
                                "f"(acc[mt][nt][0]), "f"(acc[mt][nt][1]) : "memory");
                asm volatile("st.shared.v2.f32 [%0], {%1,%2};"
                             :: "r"(base + ((r0 + 8) * PSTR + col) * 4),
                                "f"(acc[mt][nt][2]), "f"(acc[mt][nt][3]) : "memory");
            }
        }
    };
    // per-warp vector dot: out[row] = sum_j P[row][j]*v[j] (+ add[row]); rows wid*16..+15
    auto vec_dot = [&](uint32_t matB, const float* vg, uint32_t vS, uint32_t outB,
                       const float* addg, int addOff, float scale) {
        float vr[4];
        #pragma unroll
        for (int k = 0; k < 4; ++k)
            vr[k] = vg ? vg[lane + k * 32] : lds_f32(vS + (lane + k * 32) * 4);
        for (int rr = 0; rr < 16; ++rr) {
            const int row = wid * 16 + rr;
            float p = 0.f;
            #pragma unroll
            for (int k = 0; k < 4; ++k)
                p += lds_f32(matB + (row * PSTR + lane + k * 32) * 4) * vr[k];
            p = warp_red(p);
            if (lane == 0) {
                float addv = addg ? addg[addOff + row] : lds_f32(auxW + row * 4);
                asm volatile("st.shared.f32 [%0], %1;"
                             :: "r"(outB + row * 4), "f"(scale * (p + addv)) : "memory");
            }
        }
    };

    // ================= prologue: fold weights =================
    // GEMM2: Bm = Wiv @ Wv
    stage64(p0, W_in + 256 * HID);
    stage64(p1, Wv);
    CPA_WAIT_ALL();
    __syncthreads();
    zero_acc();
    gemm_tf32(p0, p1);
    vec_dot(p0, bv, 0u, auxU, b_in, 256, 1.0f);          // u = Wiv@bv + biv
    __syncthreads();
    store_acc(p2);                                        // Bm -> P2
    // GEMM1: A = Wo @ W_mo
    stage64(p0, Wo);
    stage64(p1, W_mo);
    CPA_WAIT_ALL();
    __syncthreads();
    zero_acc();
    gemm_tf32(p0, p1);
    vec_dot(p0, b_mo, 0u, auxW, bo, 0, 1.0f);             // w = Wo@b_mo + bo
    __syncthreads();
    store_acc(p0);                                        // A -> P0
    __syncthreads();
    // GEMM3: M = A @ Bm ;  c = 0.5*(A@u + w)
    zero_acc();
    gemm_tf32(p0, p2);
    vec_dot(p0, nullptr, auxU, auxC, nullptr, 0, 0.5f);   // c
    __syncthreads();
    // scatter M' = 0.5*M as bf16 into XB with the mma-B-fragment layout
    #pragma unroll
    for (int mt = 0; mt < 4; ++mt)
        #pragma unroll
        for (int nt = 0; nt < 4; ++nt)
            #pragma unroll
            for (int qq = 0; qq < 4; ++qq) {
                const int o = wm * 64 + mt * 16 + lq + ((qq >> 1) * 8);
                const int i = wn * 32 + nt * 8 + 2 * lr + (qq & 1);
                const __nv_bfloat16 hb = __float2bfloat16(0.5f * acc[mt][nt][qq]);
                const uint16_t hbits = *reinterpret_cast<const uint16_t*>(&hb);
                const int ksx = i >> 4, r = i & 15;
                const int regi = (r >> 3) & 1, half = r & 1;
                const int ntx = o >> 3;
                const int lane2 = ((o & 7) << 2) | ((r & 7) >> 1);
                const int idx = ((((ntx * 8 + ksx) * 2 + regi) * 32) + lane2) * 2 + half;
                asm volatile("st.shared.b16 [%0], %1;"
                             :: "r"(xbB + idx * 2), "h"(hbits) : "memory");
            }
    __syncthreads();

    // ---- load per-thread constants: breg (B fragments), cv (bias) ----
    uint32_t breg[4][8][2];
    #pragma unroll
    for (int nt = 0; nt < 4; ++nt)
        #pragma unroll
        for (int ks = 0; ks < 8; ++ks)
            #pragma unroll
            for (int ri = 0; ri < 2; ++ri) {
                const uint32_t i32 = (uint32_t)((((wn * 4 + nt) * 8 + ks) * 2 + ri) * 32 + lane);
                asm volatile("ld.shared.b32 %0, [%1];"
                             : "=r"(breg[nt][ks][ri]) : "r"(xbB + i32 * 4));
            }
    float cv[4][2];
    #pragma unroll
    for (int nt = 0; nt < 4; ++nt) {
        const int col = wn * 32 + nt * 8 + 2 * lr;
        cv[nt][0] = lds_f32(auxC + col * 4);
        cv[nt][1] = lds_f32(auxC + (col + 1) * 4);
    }
    __syncthreads();   // everyone done reading XB/aux before loop overwrites

    // ---- issue initial 3 tile loads (static tiles: bid + i*GRID) ----
    if (tid == 0) {
        #pragma unroll
        for (int st = 0; st < 3; ++st) {
            const int c = bid + st * GRID;
            if (c < ntiles) {
                MBAR_EXPECT(sb + OFF_MBAR + 8 * st, TILE_BYTES);
                #pragma unroll
                for (int ac = 0; ac < 4; ++ac)
                    TMA_LOAD2D(sb + (uint32_t)st * 65536u + ac * 16384, &tmX,
                               ac * 32, c * BM, sb + OFF_MBAR + 8 * st);
            }
        }
    }

    // per-thread constants for the convert pass
    const int crow = tid >> 1, ch = tid & 1;
    const uint32_t cr7 = (uint32_t)(crow & 7);
    const int rsub = lane & 15;
    const uint32_t lr7 = (uint32_t)(rsub & 7);
    const int khalf = lane >> 4;
    const uint32_t er7a = (uint32_t)(lane >> 2);
    const uint32_t einner = (uint32_t)(lane & 1) * 8;
    const uint32_t eq16b = (uint32_t)((lane & 3) >> 1);

    // ================= main loop =================
    unsigned ph = 0;
    int pend_stage = -1;
    int pend_tick = 0;
    int p = 0;
    int q = bid;
    for (;;) {
        if (q >= ntiles) break;
        const uint32_t xs = sb + (uint32_t)p * 65536u;

        MBAR_WAIT(sb + OFF_MBAR + 8 * p, (ph >> p) & 1);
        ph ^= (1u << p);

        // ---- convert fp32 XS[p] -> bf16 XB (swizzled 256B rows) ----
        {
            const uint32_t rxs = xs + (uint32_t)crow * 128;
            const uint32_t rxb = xbB + (uint32_t)crow * 256;
            #pragma unroll
            for (int j = 0; j < 8; ++j) {
                const int cj = ch * 8 + j;
                const uint32_t c32 = (uint32_t)(cj >> 2) * 16384;
                const uint32_t q0 = (uint32_t)((cj & 3) * 2);
                const uint32_t a0 = rxs + c32 + ((q0 ^ cr7) << 4);
                const uint32_t a1 = rxs + c32 + (((q0 + 1) ^ cr7) << 4);
                float x0, x1, x2, x3, y0, y1, y2, y3;
                asm volatile("ld.shared.v4.f32 {%0,%1,%2,%3}, [%4];"
                             : "=f"(x0), "=f"(x1), "=f"(x2), "=f"(x3) : "r"(a0));
                asm volatile("ld.shared.v4.f32 {%0,%1,%2,%3}, [%4];"
                             : "=f"(y0), "=f"(y1), "=f"(y2), "=f"(y3) : "r"(a1));
                const uint32_t b0 = packbf(x0, x1), b1 = packbf(x2, x3);
                const uint32_t b2 = packbf(y0, y1), b3 = packbf(y2, y3);
                const uint32_t ab = rxb + (((uint32_t)cj ^ cr7) << 4);
                asm volatile("st.shared.v4.b32 [%0], {%1,%2,%3,%4};"
                             :: "r"(ab), "r"(b0), "r"(b1), "r"(b2), "r"(b3) : "memory");
            }
        }
        __syncthreads();   // XB ready

        // ---- mma from XB ----
        float macc[4][4][4];
        #pragma unroll
        for (int mt = 0; mt < 4; ++mt)
            #pragma unroll
            for (int nt = 0; nt < 4; ++nt)
                #pragma unroll
                for (int qq = 0; qq < 4; ++qq) macc[mt][nt][qq] = 0.f;

        #pragma unroll
        for (int ks = 0; ks < 8; ++ks) {
            uint32_t a[4][4];
            const uint32_t chunk = (uint32_t)(2 * ks + khalf);
            const uint32_t csw = (chunk ^ lr7) << 4;
            #pragma unroll
            for (int mt = 0; mt < 4; ++mt) {
                const uint32_t addr =
                    xbB + (uint32_t)(wm * 64 + mt * 16 + rsub) * 256 + csw;
                asm volatile("ldmatrix.sync.aligned.m8n8.x4.shared.b16 {%0,%1,%2,%3}, [%4];"
                             : "=r"(a[mt][0]), "=r"(a[mt][1]), "=r"(a[mt][2]), "=r"(a[mt][3])
                             : "r"(addr));
            }
            #pragma unroll
            for (int mt = 0; mt < 4; ++mt)
                #pragma unroll
                for (int nt = 0; nt < 4; ++nt) {
                    asm volatile(
                        "mma.sync.aligned.m16n8k16.row.col.f32.bf16.bf16.f32 "
                        "{%0,%1,%2,%3}, {%4,%5,%6,%7}, {%8,%9}, {%0,%1,%2,%3};"
                        : "+f"(macc[mt][nt][0]), "+f"(macc[mt][nt][1]),
                          "+f"(macc[mt][nt][2]), "+f"(macc[mt][nt][3])
                        : "r"(a[mt][0]), "r"(a[mt][1]), "r"(a[mt][2]), "r"(a[mt][3]),
                          "r"(breg[nt][ks][0]), "r"(breg[nt][ks][1]));
                }
        }

        // ---- epilogue: Y = X + acc + c, in place in XS[p] ----
        {
            const uint32_t xsn = xs + (uint32_t)wn * 16384;
            #pragma unroll
            for (int mt = 0; mt < 4; ++mt) {
                const uint32_t rA = (uint32_t)(wm * 64 + mt * 16) + (uint32_t)(lane >> 2);
                const uint32_t baseA = xsn + rA * 128;
                const uint32_t baseB = xsn + (rA + 8) * 128;
                #pragma unroll
                for (int nt = 0; nt < 4; ++nt) {
                    const uint32_t q16 = (uint32_t)(nt * 2) + eq16b;
                    const uint32_t aA = baseA + ((q16 ^ er7a) << 4) + einner;
                    const uint32_t aB = baseB + ((q16 ^ er7a) << 4) + einner;
                    float f0, f1;
                    asm volatile("ld.shared.v2.f32 {%0,%1}, [%2];"
                                 : "=f"(f0), "=f"(f1) : "r"(aA));
                    f0 += macc[mt][nt][0] + cv[nt][0];
                    f1 += macc[mt][nt][1] + cv[nt][1];
                    asm volatile("st.shared.v2.f32 [%0], {%1,%2};"
                                 :: "r"(aA), "f"(f0), "f"(f1) : "memory");
                    asm volatile("ld.shared.v2.f32 {%0,%1}, [%2];"
                                 : "=f"(f0), "=f"(f1) : "r"(aB));
                    f0 += macc[mt][nt][2] + cv[nt][0];
                    f1 += macc[mt][nt][3] + cv[nt][1];
                    asm volatile("st.shared.v2.f32 [%0], {%1,%2};"
                                 :: "r"(aB), "f"(f0), "f"(f1) : "memory");
                }
            }
        }
        FENCE_ASYNC();
        __syncthreads();

        // ---- tid0: deferred reload (stage stored last iter), store cur ----
        if (tid == 0) {
            if (pend_stage >= 0) {
                asm volatile("cp.async.bulk.wait_group.read 0;" ::: "memory");
                if (pend_tick < ntiles) {
                    const uint32_t xo = sb + (uint32_t)pend_stage * 65536u;
                    MBAR_EXPECT(sb + OFF_MBAR + 8 * pend_stage, TILE_BYTES);
                    #pragma unroll
                    for (int ac = 0; ac < 4; ++ac)
                        TMA_LOAD2D(xo + ac * 16384, &tmX,
                                   ac * 32, pend_tick * BM, sb + OFF_MBAR + 8 * pend_stage);
                }
            }
            #pragma unroll
            for (int ac = 0; ac < 4; ++ac)
                TMA_STORE2D(&tmY, ac * 32, q * BM, xs + ac * 16384);
            asm volatile("cp.async.bulk.commit_group;" ::: "memory");
        }
        pend_stage = p;
        pend_tick = q + 3 * GRID;
        q += GRID;
        // rotate stage p -> p+1 mod 3; advance q mapping: tile for stage p' is
        // tracked implicitly: tiles are visited in order bid, bid+GRID, ...
        ++p;
        if (p == 3) p = 0;
    }

    if (tid == 0)
        asm volatile("cp.async.bulk.wait_group 0;" ::: "memory");
}

// ================= host ====================================================
typedef CUresult (*PFN_encodeTiled)(
    CUtensorMap*, CUtensorMapDataType, cuuint32_t, void*,
    const cuuint64_t*, const cuuint64_t*, const cuuint32_t*, const cuuint32_t*,
    CUtensorMapInterleave, CUtensorMapSwizzle, CUtensorMapL2promotion,
    CUtensorMapFloatOOBfill);

extern "C" void kernel_launch(void* const* d_in, const int* in_sizes, int n_in,
                              void* d_out, int out_size)
{
    const float* X    = (const float*)d_in[0];
    const float* Wv   = (const float*)d_in[7];
    const float* bv   = (const float*)d_in[8];
    const float* W_in = (const float*)d_in[9];
    const float* b_in = (const float*)d_in[10];
    const float* W_mo = (const float*)d_in[11];
    const float* b_mo = (const float*)d_in[12];
    const float* Wo   = (const float*)d_in[13];
    const float* bo   = (const float*)d_in[14];
    float* Y = (float*)d_out;

    const int E = in_sizes[0] / HID;
    const int ntiles = (E + BM - 1) / BM;

    void* pfn = nullptr;
    cudaDriverEntryPointQueryResult qr;
    cudaGetDriverEntryPoint("cuTensorMapEncodeTiled", &pfn, cudaEnableDefault, &qr);
    PFN_encodeTiled encode = (PFN_encodeTiled)pfn;

    CUtensorMap tmX, tmY;
    cuuint64_t dims[2] = { (cuuint64_t)HID, (cuuint64_t)E };
    cuuint64_t str[1]  = { (cuuint64_t)HID * 4 };
    cuuint32_t box[2]  = { 32, 128 };
    cuuint32_t es[2]   = { 1, 1 };
    encode(&tmX, CU_TENSOR_MAP_DATA_TYPE_FLOAT32, 2, (void*)X,
           dims, str, box, es, CU_TENSOR_MAP_INTERLEAVE_NONE,
           CU_TENSOR_MAP_SWIZZLE_128B, CU_TENSOR_MAP_L2_PROMOTION_L2_128B,
           CU_TENSOR_MAP_FLOAT_OOB_FILL_NONE);
    encode(&tmY, CU_TENSOR_MAP_DATA_TYPE_FLOAT32, 2, (void*)Y,
           dims, str, box, es, CU_TENSOR_MAP_INTERLEAVE_NONE,
           CU_TENSOR_MAP_SWIZZLE_128B, CU_TENSOR_MAP_L2_PROMOTION_L2_128B,
           CU_TENSOR_MAP_FLOAT_OOB_FILL_NONE);

    cudaFuncSetAttribute(fused_all, cudaFuncAttributeMaxDynamicSharedMemorySize, SMEM_TOTAL);
    fused_all<<<GRID, NTHREADS, SMEM_TOTAL>>>(tmX, tmY,
        Wo, W_mo, W_in, Wv, bv, b_in, b_mo, bo, ntiles);
}

// round 11
// speedup vs baseline: 1.0113x; 1.0113x over previous
#include <cuda_runtime.h>
#include <cuda.h>
#include <cuda_bf16.h>
#include <cstdint>
#include <cstddef>

#define HID 128
#define BM 128
#define TILE_BYTES 65536
#define GRID 148
#define NTHREADS 512

// ---------------- device scratch ----------------
__device__ float g_A[HID * HID];                 // Wo @ W_mo
__device__ float g_B[HID * HID];                 // Wiv @ Wv
__device__ float g_u[HID];
__device__ float g_w[HID];
__device__ __nv_bfloat16 g_Bf[16 * 8 * 2 * 32 * 2]; // 0.5*M^T bf16, mma-B-fragment layout
__device__ float g_c[HID];                       // 0.5*(A@u + w)
__device__ unsigned int g_tile_ctr;              // dynamic tile tickets (reset in prep1)

__device__ __forceinline__ uint32_t smem_u32(const void* p) {
    uint32_t a;
    asm("{ .reg .u64 t; cvta.to.shared.u64 t, %1; cvt.u32.u64 %0, t; }" : "=r"(a) : "l"(p));
    return a;
}
__device__ __forceinline__ float warp_red(float p) {
    p += __shfl_xor_sync(0xffffffffu, p, 16);
    p += __shfl_xor_sync(0xffffffffu, p, 8);
    p += __shfl_xor_sync(0xffffffffu, p, 4);
    p += __shfl_xor_sync(0xffffffffu, p, 2);
    p += __shfl_xor_sync(0xffffffffu, p, 1);
    return p;
}
#define CPA16(dst, src) \
    asm volatile("cp.async.cg.shared.global [%0], [%1], 16;" :: "r"(dst), "l"(src))
#define CPA_WAIT_ALL() \
    asm volatile("cp.async.commit_group;\ncp.async.wait_group 0;" ::: "memory")

// ================= prep1: A = Wo@W_mo, B = Wiv@Wv, u, w ===================
// 64 blocks x 2 rows; full weight matrices staged in one cp.async burst.
__global__ __launch_bounds__(256) void prep1(
    const float* __restrict__ Wo, const float* __restrict__ W_mo,
    const float* __restrict__ W_in, const float* __restrict__ Wv,
    const float* __restrict__ bv, const float* __restrict__ b_in,
    const float* __restrict__ b_mo, const float* __restrict__ bo)
{
    extern __shared__ float sm[];          // sW[16384] | sV[16384]
    float* sW = sm;
    float* sV = sm + 16384;
    __shared__ float sWo[2][HID], sWiv[2][HID];

    const int b = blockIdx.x, t = threadIdx.x;
    const int r0 = b * 2;

    if (b == 0 && t == 0) g_tile_ctr = 0;

    const uint32_t sWa  = smem_u32(sW);
    const uint32_t sVa  = smem_u32(sV);
    const uint32_t sWoA = smem_u32(&sWo[0][0]);
    const uint32_t sWiA = smem_u32(&sWiv[0][0]);
    if (t < 64) {
        CPA16(sWoA + t * 16, Wo + r0 * HID + t * 4);
    } else if (t < 128) {
        const int i = t - 64;
        CPA16(sWiA + i * 16, W_in + (256 + r0) * HID + i * 4);
    }
    #pragma unroll
    for (int q = 0; q < 16; ++q) {
        const int i = q * 256 + t;
        CPA16(sWa + i * 16, W_mo + i * 4);
        CPA16(sVa + i * 16, Wv + i * 4);
    }
    CPA_WAIT_ALL();
    __syncthreads();

    if (t < HID) {
        float a0 = 0.f, a1 = 0.f;
        #pragma unroll
        for (int j = 0; j < HID; ++j) {
            const float m = sW[j * HID + t];
            a0 += sWo[0][j] * m;
            a1 += sWo[1][j] * m;
        }
        g_A[(r0 + 0) * HID + t] = a0;
        g_A[(r0 + 1) * HID + t] = a1;
    } else {
        const int c = t - HID;
        float a0 = 0.f, a1 = 0.f;
        #pragma unroll
        for (int j = 0; j < HID; ++j) {
            const float m = sV[j * HID + c];
            a0 += sWiv[0][j] * m;
            a1 += sWiv[1][j] * m;
        }
        g_B[(r0 + 0) * HID + c] = a0;
        g_B[(r0 + 1) * HID + c] = a1;
    }

    const int wid = t >> 5, lane = t & 31;
    if (wid < 2) {
        float p = 0.f;
        #pragma unroll
        for (int j = lane; j < HID; j += 32) p += sWiv[wid][j] * bv[j];
        p = warp_red(p);
        if (lane == 0) g_u[r0 + wid] = p + b_in[256 + r0 + wid];
    } else if (wid < 4) {
        const int rr = wid - 2;
        float p = 0.f;
        #pragma unroll
        for (int j = lane; j < HID; j += 32) p += sWo[rr][j] * b_mo[j];
        p = warp_red(p);
        if (lane == 0) g_w[r0 + rr] = p + bo[r0 + rr];
    }
}

// ================= prep2: Bf = bf16(0.5*A@B) fragment layout; c ===========
__global__ __launch_bounds__(256) void prep2()
{
    extern __shared__ float sm[];          // sB[16384]
    float* sB = sm;
    __shared__ float sA[2][HID];

    const int b = blockIdx.x, t = threadIdx.x;
    const int r0 = b * 2;

    const uint32_t sBa = smem_u32(sB);
    const uint32_t sAa = smem_u32(&sA[0][0]);
    if (t < 64)
        CPA16(sAa + t * 16, g_A + r0 * HID + t * 4);
    #pragma unroll
    for (int q = 0; q < 16; ++q) {
        const int i = q * 256 + t;
        CPA16(sBa + i * 16, g_B + i * 4);
    }
    CPA_WAIT_ALL();
    __syncthreads();

    if (t < HID) {
        float a0 = 0.f, a1 = 0.f;
        #pragma unroll
        for (int j = 0; j < HID; ++j) {
            const float m = sB[j * HID + t];
            a0 += sA[0][j] * m;
            a1 += sA[1][j] * m;
        }
        float mv[2] = { 0.5f * a0, 0.5f * a1 };
        const int i = t;
        const int ks = i >> 4;
        const int r  = i & 15;
        const int regi = (r >> 3) & 1;
        const int half = r & 1;
        #pragma unroll
        for (int rr = 0; rr < 2; ++rr) {
            const int o = r0 + rr;
            const int nt = o >> 3;
            const int lane2 = ((o & 7) << 2) | ((r & 7) >> 1);
            const int idx = ((((nt * 8 + ks) * 2 + regi) * 32) + lane2) * 2 + half;
            g_Bf[idx] = __float2bfloat16(mv[rr]);
        }
    }

    const int wid = t >> 5, lane = t & 31;
    if (wid < 2) {
        const int o = r0 + wid;
        float p = 0.f;
        #pragma unroll
        for (int j = lane; j < HID; j += 32) p += sA[wid][j] * g_u[j];
        p = warp_red(p);
        if (lane == 0) g_c[o] = 0.5f * (p + g_w[o]);
    }
}

// ================= main =====================================================
// smem: XS0 @0, XS1 @65536, XS2 @131072 (each 64KB fp32 SW128),
//       XB @196608 (32KB bf16), mbar full0/1/2 @229376, sTick[3] @229400
#define OFF_XS0  0u
#define OFF_XS1  65536u
#define OFF_XS2  131072u
#define OFF_XB   196608u
#define OFF_MBAR 229376u
#define OFF_TICK 229400u
#define SMEM_TOTAL 229440

#define MBAR_INIT(a, c) \
    asm volatile("mbarrier.init.shared.b64 [%0], %1;" :: "r"(a), "r"(c) : "memory")
#define MBAR_EXPECT(a, b) \
    asm volatile("mbarrier.arrive.expect_tx.shared.b64 _, [%0], %1;" :: "r"(a), "r"(b) : "memory")
#define MBAR_WAIT(mbar, par) do {                                             \
    uint32_t _m = (mbar); uint32_t _p = (par); uint32_t _d;                   \
    asm volatile("{\n\t.reg .pred p;\n\t"                                     \
        "mbarrier.try_wait.parity.acquire.cta.shared::cta.b64 p, [%1], %2;\n\t" \
        "selp.b32 %0, 1, 0, p;\n\t}"                                          \
        : "=r"(_d) : "r"(_m), "r"(_p) : "memory");                            \
    if (!_d) {                                                                \
        asm volatile("{\n\t.reg .pred P1;\n\t"                                \
            "W_%=:\n\t"                                                       \
            "mbarrier.try_wait.parity.acquire.cta.shared::cta.b64 P1, [%0], %1, 0x989680;\n\t" \
            "@P1 bra.uni D_%=;\n\t"                                           \
            "bra.uni W_%=;\n\t"                                               \
            "D_%=:\n\t}" :: "r"(_m), "r"(_p) : "memory");                     \
    }                                                                         \
} while (0)

#define TMA_LOAD2D(dst, map, x, y, mb) \
    asm volatile("cp.async.bulk.tensor.2d.shared::cta.global.tile.mbarrier::complete_tx::bytes " \
                 "[%0], [%1, {%2, %3}], [%4];" \
                 :: "r"(dst), "l"(map), "r"(x), "r"(y), "r"(mb) : "memory")
#define TMA_STORE2D(map, x, y, src) \
    asm volatile("cp.async.bulk.tensor.2d.global.shared::cta.tile.bulk_group " \
                 "[%0, {%1, %2}], [%3];" \
                 :: "l"(map), "r"(x), "r"(y), "r"(src) : "memory")
#define FENCE_ASYNC() asm volatile("fence.proxy.async.shared::cta;" ::: "memory")

__device__ __forceinline__ uint32_t packbf(float lo, float hi) {
    uint32_t d;
    asm("cvt.rn.bf16x2.f32 %0, %1, %2;" : "=r"(d) : "f"(hi), "f"(lo));
    return d;
}

__global__ __launch_bounds__(NTHREADS, 1) void fused_main(
    const __grid_constant__ CUtensorMap tmX,
    const __grid_constant__ CUtensorMap tmY,
    int ntiles)
{
    extern __shared__ __align__(1024) unsigned char smem_raw[];
    const uint32_t sb = smem_u32(smem_raw);
    const int tid  = threadIdx.x;
    const int lane = tid & 31, wid = tid >> 5;
    const int wm = wid & 3, wn = wid >> 2;      // 4(m) x 4(n) warp grid
    const uint32_t mb_full[3] = { sb + OFF_MBAR, sb + OFF_MBAR + 8, sb + OFF_MBAR + 16 };
    const uint32_t xs_a[3] = { sb + OFF_XS0, sb + OFF_XS1, sb + OFF_XS2 };
    const uint32_t xb = sb + OFF_XB;
    unsigned* sTick = reinterpret_cast<unsigned*>(smem_raw + (OFF_TICK));

    // ---- B fragments into registers (constant across tiles) ----
    uint32_t breg[4][8][2];
    {
        const uint32_t* bp = reinterpret_cast<const uint32_t*>(g_Bf);
        #pragma unroll
        for (int nt = 0; nt < 4; ++nt)
            #pragma unroll
            for (int ks = 0; ks < 8; ++ks)
                #pragma unroll
                for (int ri = 0; ri < 2; ++ri)
                    breg[nt][ks][ri] =
                        bp[(((wn * 4 + nt) * 8 + ks) * 2 + ri) * 32 + lane];
    }
    // ---- c bias (per-thread cols) ----
    float cv[4][2];
    #pragma unroll
    for (int nt = 0; nt < 4; ++nt) {
        const int col = wn * 32 + nt * 8 + 2 * (lane & 3);
        cv[nt][0] = g_c[col];
        cv[nt][1] = g_c[col + 1];
    }

    if (tid == 0) {
        MBAR_INIT(mb_full[0], 1);
        MBAR_INIT(mb_full[1], 1);
        MBAR_INIT(mb_full[2], 1);
    }
    __syncthreads();

    // ---- prologue: 3 tickets, 3 loads ----
    if (tid == 0) {
        #pragma unroll
        for (int st = 0; st < 3; ++st) {
            const unsigned c = atomicAdd(&g_tile_ctr, 1u);
            sTick[st] = c;
            if (c < (unsigned)ntiles) {
                MBAR_EXPECT(mb_full[st], TILE_BYTES);
                #pragma unroll
                for (int ac = 0; ac < 4; ++ac)
                    TMA_LOAD2D(xs_a[st] + ac * 16384, &tmX, ac * 32, (int)c * BM, mb_full[st]);
            }
        }
    }
    __syncthreads();

    // per-thread constants for the convert pass (512 threads: 4 per row)
    const int crow = tid >> 2, ch = tid & 3;
    const uint32_t cr7 = (uint32_t)(crow & 7);
    // ldmatrix constants
    const int rsub = lane & 15;
    const uint32_t lr7 = (uint32_t)(rsub & 7);
    const int khalf = lane >> 4;
    // epilogue constants
    const uint32_t er7a = (uint32_t)(lane >> 2);
    const uint32_t einner = (uint32_t)(lane & 1) * 8;
    const uint32_t eq16b = (uint32_t)((lane & 3) >> 1);

    unsigned ph = 0;
    int pend_stage = -1;
    unsigned pend_tick = 0;

    for (int i = 0; ; ++i) {
        const int p = i % 3;
        const unsigned q = sTick[p];
        if (q >= (unsigned)ntiles) break;

        // wait X tile for stage p
        MBAR_WAIT(mb_full[p], (ph >> p) & 1);
        ph ^= (1u << p);

        // ---- convert fp32 XS[p] -> bf16 XB (swizzled 256B rows) ----
        {
            const uint32_t rxs = xs_a[p] + (uint32_t)crow * 128;
            const uint32_t rxb = xb + (uint32_t)crow * 256;
            #pragma unroll
            for (int j = 0; j < 4; ++j) {
                const int cj = ch * 4 + j;
                const uint32_t c32 = (uint32_t)(cj >> 2) * 16384;
                const uint32_t q0 = (uint32_t)((cj & 3) * 2);
                const uint32_t a0 = rxs + c32 + ((q0 ^ cr7) << 4);
                const uint32_t a1 = rxs + c32 + (((q0 + 1) ^ cr7) << 4);
                float x0, x1, x2, x3, y0, y1, y2, y3;
                asm volatile("ld.shared.v4.f32 {%0,%1,%2,%3}, [%4];"
                             : "=f"(x0), "=f"(x1), "=f"(x2), "=f"(x3) : "r"(a0));
                asm volatile("ld.shared.v4.f32 {%0,%1,%2,%3}, [%4];"
                             : "=f"(y0), "=f"(y1), "=f"(y2), "=f"(y3) : "r"(a1));
                const uint32_t p0 = packbf(x0, x1), p1 = packbf(x2, x3);
                const uint32_t p2 = packbf(y0, y1), p3 = packbf(y2, y3);
                const uint32_t ab = rxb + (((uint32_t)cj ^ cr7) << 4);
                asm volatile("st.shared.v4.b32 [%0], {%1,%2,%3,%4};"
                             :: "r"(ab), "r"(p0), "r"(p1), "r"(p2), "r"(p3) : "memory");
            }
        }
        __syncthreads();   // XB ready

        // ---- mma from XB: warp tile m32 x n32 ----
        float acc[2][4][4];
        #pragma unroll
        for (int mt = 0; mt < 2; ++mt)
            #pragma unroll
            for (int nt = 0; nt < 4; ++nt)
                #pragma unroll
                for (int qq = 0; qq < 4; ++qq) acc[mt][nt][qq] = 0.f;

        #pragma unroll
        for (int ks = 0; ks < 8; ++ks) {
            uint32_t a[2][4];
            const uint32_t chunk = (uint32_t)(2 * ks + khalf);
            const uint32_t csw = (chunk ^ lr7) << 4;
            #pragma unroll
            for (int mt = 0; mt < 2; ++mt) {
                const uint32_t addr =
                    xb + (uint32_t)(wm * 32 + mt * 16 + rsub) * 256 + csw;
                asm volatile("ldmatrix.sync.aligned.m8n8.x4.shared.b16 {%0,%1,%2,%3}, [%4];"
                             : "=r"(a[mt][0]), "=r"(a[mt][1]), "=r"(a[mt][2]), "=r"(a[mt][3])
                             : "r"(addr));
            }
            #pragma unroll
            for (int mt = 0; mt < 2; ++mt)
                #pragma unroll
                for (int nt = 0; nt < 4; ++nt) {
                    asm volatile(
                        "mma.sync.aligned.m16n8k16.row.col.f32.bf16.bf16.f32 "
                        "{%0,%1,%2,%3}, {%4,%5,%6,%7}, {%8,%9}, {%0,%1,%2,%3};"
                        : "+f"(acc[mt][nt][0]), "+f"(acc[mt][nt][1]),
                          "+f"(acc[mt][nt][2]), "+f"(acc[mt][nt][3])
                        : "r"(a[mt][0]), "r"(a[mt][1]), "r"(a[mt][2]), "r"(a[mt][3]),
                          "r"(breg[nt][ks][0]), "r"(breg[nt][ks][1]));
                }
        }

        // ---- epilogue: Y = X + acc + c, in place in XS[p] ----
        {
            const uint32_t xsn = xs_a[p] + (uint32_t)wn * 16384;
            #pragma unroll
            for (int mt = 0; mt < 2; ++mt) {
                const uint32_t rA = (uint32_t)(wm * 32 + mt * 16) + (uint32_t)(lane >> 2);
                const uint32_t rB = rA + 8;
                const uint32_t baseA = xsn + rA * 128;
                const uint32_t baseB = xsn + rB * 128;
                #pragma unroll
                for (int nt = 0; nt < 4; ++nt) {
                    const uint32_t q16 = (uint32_t)(nt * 2) + eq16b;
                    const uint32_t aA = baseA + ((q16 ^ er7a) << 4) + einner;
                    const uint32_t aB = baseB + ((q16 ^ er7a) << 4) + einner;
                    float f0, f1;
                    asm volatile("ld.shared.v2.f32 {%0,%1}, [%2];"
                                 : "=f"(f0), "=f"(f1) : "r"(aA));
                    f0 += acc[mt][nt][0] + cv[nt][0];
                    f1 += acc[mt][nt][1] + cv[nt][1];
                    asm volatile("st.shared.v2.f32 [%0], {%1,%2};"
                                 :: "r"(aA), "f"(f0), "f"(f1) : "memory");
                    asm volatile("ld.shared.v2.f32 {%0,%1}, [%2];"
                                 : "=f"(f0), "=f"(f1) : "r"(aB));
                    f0 += acc[mt][nt][2] + cv[nt][0];
                    f1 += acc[mt][nt][3] + cv[nt][1];
                    asm volatile("st.shared.v2.f32 [%0], {%1,%2};"
                                 :: "r"(aB), "f"(f0), "f"(f1) : "memory");
                }
            }
        }
        FENCE_ASYNC();
        __syncthreads();   // epilogue done in XS[p]

        // ---- tid0: deferred reload (stage stored last iter), store cur, new ticket ----
        if (tid == 0) {
            if (pend_stage >= 0) {
                asm volatile("cp.async.bulk.wait_group.read 0;" ::: "memory");
                if (pend_tick < (unsigned)ntiles) {
                    MBAR_EXPECT(mb_full[pend_stage], TILE_BYTES);
                    #pragma unroll
                    for (int ac = 0; ac < 4; ++ac)
                        TMA_LOAD2D(xs_a[pend_stage] + ac * 16384, &tmX,
                                   ac * 32, (int)pend_tick * BM, mb_full[pend_stage]);
                }
            }
            #pragma unroll
            for (int ac = 0; ac < 4; ++ac)
                TMA_STORE2D(&tmY, ac * 32, (int)q * BM, xs_a[p] + ac * 16384);
            asm volatile("cp.async.bulk.commit_group;" ::: "memory");
            const unsigned nn = atomicAdd(&g_tile_ctr, 1u);
            sTick[p] = nn;
            pend_stage = p;
            pend_tick = nn;
        }
    }

    if (tid == 0)
        asm volatile("cp.async.bulk.wait_group 0;" ::: "memory");
}

// ================= host ====================================================
typedef CUresult (*PFN_encodeTiled)(
    CUtensorMap*, CUtensorMapDataType, cuuint32_t, void*,
    const cuuint64_t*, const cuuint64_t*, const cuuint32_t*, const cuuint32_t*,
    CUtensorMapInterleave, CUtensorMapSwizzle, CUtensorMapL2promotion,
    CUtensorMapFloatOOBfill);

extern "C" void kernel_launch(void* const* d_in, const int* in_sizes, int n_in,
                              void* d_out, int out_size)
{
    const float* X    = (const float*)d_in[0];
    const float* Wv   = (const float*)d_in[7];
    const float* bv   = (const float*)d_in[8];
    const float* W_in = (const float*)d_in[9];
    const float* b_in = (const float*)d_in[10];
    const float* W_mo = (const float*)d_in[11];
    const float* b_mo = (const float*)d_in[12];
    const float* Wo   = (const float*)d_in[13];
    const float* bo   = (const float*)d_in[14];
    float* Y = (float*)d_out;

    const int E = in_sizes[0] / HID;
    const int ntiles = (E + BM - 1) / BM;

    cudaFuncSetAttribute(prep1, cudaFuncAttributeMaxDynamicSharedMemorySize, 131072);
    cudaFuncSetAttribute(prep2, cudaFuncAttributeMaxDynamicSharedMemorySize, 65536);
    prep1<<<64, 256, 131072>>>(Wo, W_mo, W_in, Wv, bv, b_in, b_mo, bo);
    prep2<<<64, 256, 65536>>>();

    void* pfn = nullptr;
    cudaDriverEntryPointQueryResult qr;
    cudaGetDriverEntryPoint("cuTensorMapEncodeTiled", &pfn, cudaEnableDefault, &qr);
    PFN_encodeTiled encode = (PFN_encodeTiled)pfn;

    CUtensorMap tmX, tmY;
    cuuint64_t dims[2] = { (cuuint64_t)HID, (cuuint64_t)E };
    cuuint64_t str[1]  = { (cuuint64_t)HID * 4 };
    cuuint32_t box[2]  = { 32, 128 };
    cuuint32_t es[2]   = { 1, 1 };
    encode(&tmX, CU_TENSOR_MAP_DATA_TYPE_FLOAT32, 2, (void*)X,
           dims, str, box, es, CU_TENSOR_MAP_INTERLEAVE_NONE,
           CU_TENSOR_MAP_SWIZZLE_128B, CU_TENSOR_MAP_L2_PROMOTION_L2_128B,
           CU_TENSOR_MAP_FLOAT_OOB_FILL_NONE);
    encode(&tmY, CU_TENSOR_MAP_DATA_TYPE_FLOAT32, 2, (void*)Y,
           dims, str, box, es, CU_TENSOR_MAP_INTERLEAVE_NONE,
           CU_TENSOR_MAP_SWIZZLE_128B, CU_TENSOR_MAP_L2_PROMOTION_L2_128B,
           CU_TENSOR_MAP_FLOAT_OOB_FILL_NONE);

    cudaFuncSetAttribute(fused_main, cudaFuncAttributeMaxDynamicSharedMemorySize, SMEM_TOTAL);
    fused_main<<<GRID, NTHREADS, SMEM_TOTAL>>>(tmX, tmY, ntiles);
}

// round 12
// speedup vs baseline: 1.0984x; 1.0861x over previous
#include <cuda_runtime.h>
#include <cuda.h>
#include <cuda_bf16.h>
#include <cstdint>
#include <cstddef>

#define HID 128
#define BM 64
#define TILE_BYTES 32768
#define GRID 148
#define NTHREADS 256

// ---------------- device scratch ----------------
__device__ float g_B[HID * HID];                 // Wiv @ Wv
__device__ float g_u[HID];
__device__ __nv_bfloat16 g_Bf[16 * 8 * 2 * 32 * 2]; // 0.5*M^T bf16, fragment layout
__device__ float g_c[HID];
__device__ unsigned int g_tile_ctr;
__device__ unsigned int g_sync;                  // epoch barrier (monotonic)

__device__ __forceinline__ uint32_t smem_u32(const void* p) {
    uint32_t a;
    asm("{ .reg .u64 t; cvta.to.shared.u64 t, %1; cvt.u32.u64 %0, t; }" : "=r"(a) : "l"(p));
    return a;
}
__device__ __forceinline__ float warp_red(float p) {
    p += __shfl_xor_sync(0xffffffffu, p, 16);
    p += __shfl_xor_sync(0xffffffffu, p, 8);
    p += __shfl_xor_sync(0xffffffffu, p, 4);
    p += __shfl_xor_sync(0xffffffffu, p, 2);
    p += __shfl_xor_sync(0xffffffffu, p, 1);
    return p;
}
__device__ __forceinline__ uint32_t packbf(float lo, float hi) {
    uint32_t d;
    asm("cvt.rn.bf16x2.f32 %0, %1, %2;" : "=r"(d) : "f"(hi), "f"(lo));
    return d;
}
#define CPA16(dst, src) \
    asm volatile("cp.async.cg.shared.global [%0], [%1], 16;" :: "r"(dst), "l"(src))
#define CPA_WAIT_ALL() \
    asm volatile("cp.async.commit_group;\ncp.async.wait_group 0;" ::: "memory")

// ================= prep (single kernel, 64 blocks x 2 rows) ===============
__global__ __launch_bounds__(256) void prep(
    const float* __restrict__ Wo, const float* __restrict__ W_mo,
    const float* __restrict__ W_in, const float* __restrict__ Wv,
    const float* __restrict__ bv, const float* __restrict__ b_in,
    const float* __restrict__ b_mo, const float* __restrict__ bo)
{
    extern __shared__ float sm[];          // sW[16384] | sV[16384]
    float* sW = sm;
    float* sV = sm + 16384;
    __shared__ float sWo[2][HID], sWiv[2][HID], sAsh[2][HID], sw_own[2];

    const int b = blockIdx.x, t = threadIdx.x;
    const int r0 = b * 2;
    if (b == 0 && t == 0) g_tile_ctr = 0;

    const uint32_t sWa  = smem_u32(sW);
    const uint32_t sVa  = smem_u32(sV);
    const uint32_t sWoA = smem_u32(&sWo[0][0]);
    const uint32_t sWiA = smem_u32(&sWiv[0][0]);
    if (t < 64) {
        CPA16(sWoA + t * 16, Wo + r0 * HID + t * 4);
    } else if (t < 128) {
        const int i = t - 64;
        CPA16(sWiA + i * 16, W_in + (256 + r0) * HID + i * 4);
    }
    #pragma unroll
    for (int q = 0; q < 16; ++q) {
        const int i = q * 256 + t;
        CPA16(sWa + i * 16, W_mo + i * 4);
        CPA16(sVa + i * 16, Wv + i * 4);
    }
    CPA_WAIT_ALL();
    __syncthreads();

    const int wid = t >> 5, lane = t & 31;
    if (t < HID) {
        float a0 = 0.f, a1 = 0.f;
        #pragma unroll
        for (int j = 0; j < HID; ++j) {
            const float m = sW[j * HID + t];
            a0 += sWo[0][j] * m;
            a1 += sWo[1][j] * m;
        }
        sAsh[0][t] = a0;                   // A rows stay local
        sAsh[1][t] = a1;
    } else {
        const int c = t - HID;
        float a0 = 0.f, a1 = 0.f;
        #pragma unroll
        for (int j = 0; j < HID; ++j) {
            const float m = sV[j * HID + c];
            a0 += sWiv[0][j] * m;
            a1 += sWiv[1][j] * m;
        }
        g_B[(r0 + 0) * HID + c] = a0;
        g_B[(r0 + 1) * HID + c] = a1;
    }
    if (wid < 2) {
        float p = 0.f;
        #pragma unroll
        for (int j = lane; j < HID; j += 32) p += sWiv[wid][j] * bv[j];
        p = warp_red(p);
        if (lane == 0) g_u[r0 + wid] = p + b_in[256 + r0 + wid];
    } else if (wid < 4) {
        const int rr = wid - 2;
        float p = 0.f;
        #pragma unroll
        for (int j = lane; j < HID; j += 32) p += sWo[rr][j] * b_mo[j];
        p = warp_red(p);
        if (lane == 0) sw_own[rr] = p + bo[r0 + rr];
    }
    __threadfence();                       // publish g_B / g_u device-wide
    __syncthreads();

    // inter-block epoch barrier (all 64 blocks co-resident; replay-safe)
    if (t == 0) {
        const unsigned v = atomicAdd(&g_sync, 1u);
        const unsigned target = ((v >> 6) + 1u) << 6;
        unsigned cur;
        do {
            asm volatile("ld.volatile.global.u32 %0, [%1];" : "=r"(cur) : "l"(&g_sync));
        } while (cur < target);
    }
    __syncthreads();

    // phase 2: M rows = A_own @ B(full), scatter bf16 fragments; c
    #pragma unroll
    for (int q = 0; q < 16; ++q) {
        const int i = q * 256 + t;
        CPA16(sWa + i * 16, g_B + i * 4);
    }
    CPA_WAIT_ALL();
    __syncthreads();

    if (t < HID) {
        float m0 = 0.f, m1 = 0.f;
        #pragma unroll
        for (int j = 0; j < HID; ++j) {
            const float v = sW[j * HID + t];
            m0 += sAsh[0][j] * v;
            m1 += sAsh[1][j] * v;
        }
        const int i = t;
        const int ks = i >> 4, r = i & 15;
        const int regi = (r >> 3) & 1, half = r & 1;
        #pragma unroll
        for (int rr = 0; rr < 2; ++rr) {
            const int o = r0 + rr;
            const int nt = o >> 3;
            const int lane2 = ((o & 7) << 2) | ((r & 7) >> 1);
            const int idx = ((((nt * 8 + ks) * 2 + regi) * 32) + lane2) * 2 + half;
            g_Bf[idx] = __float2bfloat16(0.5f * (rr ? m1 : m0));
        }
    }
    if (wid < 2) {
        float p = 0.f;
        #pragma unroll
        for (int j = lane; j < HID; j += 32) p += sAsh[wid][j] * g_u[j];
        p = warp_red(p);
        if (lane == 0) g_c[r0 + wid] = 0.5f * (p + sw_own[wid]);
    }
}

// ================= main =====================================================
// smem: XS0..3 @0/32768/65536/98304 (32KB fp32 SW128 each),
//       XB0 @131072, XB1 @147456 (16KB bf16 each),
//       mbar[4] @163840, sTick[4] @163872
#define OFF_XB0  131072u
#define OFF_XB1  147456u
#define OFF_MBAR 163840u
#define OFF_TICK 163872u
#define SMEM_TOTAL 163904

#define MBAR_INIT(a, c) \
    asm volatile("mbarrier.init.shared.b64 [%0], %1;" :: "r"(a), "r"(c) : "memory")
#define MBAR_EXPECT(a, b) \
    asm volatile("mbarrier.arrive.expect_tx.shared.b64 _, [%0], %1;" :: "r"(a), "r"(b) : "memory")
#define MBAR_WAIT(mbar, par) do {                                             \
    uint32_t _m = (mbar); uint32_t _p = (par); uint32_t _d;                   \
    asm volatile("{\n\t.reg .pred p;\n\t"                                     \
        "mbarrier.try_wait.parity.acquire.cta.shared::cta.b64 p, [%1], %2;\n\t" \
        "selp.b32 %0, 1, 0, p;\n\t}"                                          \
        : "=r"(_d) : "r"(_m), "r"(_p) : "memory");                            \
    if (!_d) {                                                                \
        asm volatile("{\n\t.reg .pred P1;\n\t"                                \
            "W_%=:\n\t"                                                       \
            "mbarrier.try_wait.parity.acquire.cta.shared::cta.b64 P1, [%0], %1, 0x989680;\n\t" \
            "@P1 bra.uni D_%=;\n\t"                                           \
            "bra.uni W_%=;\n\t"                                               \
            "D_%=:\n\t}" :: "r"(_m), "r"(_p) : "memory");                     \
    }                                                                         \
} while (0)

#define TMA_LOAD2D(dst, map, x, y, mb) \
    asm volatile("cp.async.bulk.tensor.2d.shared::cta.global.tile.mbarrier::complete_tx::bytes " \
                 "[%0], [%1, {%2, %3}], [%4];" \
                 :: "r"(dst), "l"(map), "r"(x), "r"(y), "r"(mb) : "memory")
#define TMA_STORE2D(map, x, y, src) \
    asm volatile("cp.async.bulk.tensor.2d.global.shared::cta.tile.bulk_group " \
                 "[%0, {%1, %2}], [%3];" \
                 :: "l"(map), "r"(x), "r"(y), "r"(src) : "memory")
#define FENCE_ASYNC() asm volatile("fence.proxy.async.shared::cta;" ::: "memory")

__global__ __launch_bounds__(NTHREADS, 1) void fused_main(
    const __grid_constant__ CUtensorMap tmX,
    const __grid_constant__ CUtensorMap tmY,
    int ntiles)
{
    extern __shared__ __align__(1024) unsigned char smem_raw[];
    const uint32_t sb = smem_u32(smem_raw);
    const int tid  = threadIdx.x;
    const int lane = tid & 31, wid = tid >> 5;
    const int wm = wid & 1, wn = wid >> 1;      // 2(m) x 4(n) warp grid
    const uint32_t xs_a[4] = { sb, sb + 32768u, sb + 65536u, sb + 98304u };
    const uint32_t xb_a[2] = { sb + OFF_XB0, sb + OFF_XB1 };
    unsigned* sTick = reinterpret_cast<unsigned*>(smem_raw + OFF_TICK);

    // ---- B fragments in registers ----
    uint32_t breg[4][8][2];
    {
        const uint32_t* bp = reinterpret_cast<const uint32_t*>(g_Bf);
        #pragma unroll
        for (int nt = 0; nt < 4; ++nt)
            #pragma unroll
            for (int ks = 0; ks < 8; ++ks)
                #pragma unroll
                for (int ri = 0; ri < 2; ++ri)
                    breg[nt][ks][ri] =
                        bp[(((wn * 4 + nt) * 8 + ks) * 2 + ri) * 32 + lane];
    }
    float cv[4][2];
    #pragma unroll
    for (int nt = 0; nt < 4; ++nt) {
        const int col = wn * 32 + nt * 8 + 2 * (lane & 3);
        cv[nt][0] = g_c[col];
        cv[nt][1] = g_c[col + 1];
    }

    if (tid == 0) {
        #pragma unroll
        for (int st = 0; st < 4; ++st) MBAR_INIT(sb + OFF_MBAR + 8 * st, 1);
    }
    __syncthreads();

    // prologue: 4 tickets, 4 loads
    if (tid == 0) {
        #pragma unroll
        for (int st = 0; st < 4; ++st) {
            const unsigned c = atomicAdd(&g_tile_ctr, 1u);
            sTick[st] = c;
            if (c < (unsigned)ntiles) {
                MBAR_EXPECT(sb + OFF_MBAR + 8 * st, TILE_BYTES);
                #pragma unroll
                for (int ac = 0; ac < 4; ++ac)
                    TMA_LOAD2D(xs_a[st] + ac * 8192, &tmX, ac * 32, (int)c * BM,
                               sb + OFF_MBAR + 8 * st);
            }
        }
    }
    __syncthreads();

    // per-thread constants
    const int crow = tid >> 2, ch = tid & 3;        // convert: 64 rows x 4 threads
    const uint32_t cr7 = (uint32_t)(crow & 7);
    const int rsub = lane & 15;
    const uint32_t lr7 = (uint32_t)(rsub & 7);
    const int khalf = lane >> 4;
    const uint32_t er7a = (uint32_t)(lane >> 2);
    const uint32_t einner = (uint32_t)(lane & 1) * 8;
    const uint32_t eq16b = (uint32_t)((lane & 3) >> 1);

    auto convert = [&](uint32_t xs, uint32_t xbuf) {
        const uint32_t rxs = xs + (uint32_t)crow * 128;
        const uint32_t rxb = xbuf + (uint32_t)crow * 256;
        #pragma unroll
        for (int j = 0; j < 4; ++j) {
            const int cj = ch * 4 + j;
            const uint32_t c32 = (uint32_t)(cj >> 2) * 8192;
            const uint32_t q0 = (uint32_t)((cj & 3) * 2);
            const uint32_t a0 = rxs + c32 + ((q0 ^ cr7) << 4);
            const uint32_t a1 = rxs + c32 + (((q0 + 1) ^ cr7) << 4);
            float x0, x1, x2, x3, y0, y1, y2, y3;
            asm volatile("ld.shared.v4.f32 {%0,%1,%2,%3}, [%4];"
                         : "=f"(x0), "=f"(x1), "=f"(x2), "=f"(x3) : "r"(a0));
            asm volatile("ld.shared.v4.f32 {%0,%1,%2,%3}, [%4];"
                         : "=f"(y0), "=f"(y1), "=f"(y2), "=f"(y3) : "r"(a1));
            const uint32_t p0 = packbf(x0, x1), p1 = packbf(x2, x3);
            const uint32_t p2 = packbf(y0, y1), p3 = packbf(y2, y3);
            const uint32_t ab = rxb + (((uint32_t)cj ^ cr7) << 4);
            asm volatile("st.shared.v4.b32 [%0], {%1,%2,%3,%4};"
                         :: "r"(ab), "r"(p0), "r"(p1), "r"(p2), "r"(p3) : "memory");
        }
    };

    // pre-loop: convert tile0 -> XB0
    unsigned ph = 0;
    {
        const unsigned q0 = sTick[0];
        if (q0 < (unsigned)ntiles) {
            MBAR_WAIT(sb + OFF_MBAR, 0);
            ph ^= 1u;
            convert(xs_a[0], xb_a[0]);
        }
    }
    __syncthreads();

    int pend_stage = -1;
    unsigned pend_tick = 0;

    for (int i = 0; ; ++i) {
        const int sj = i & 3;
        const unsigned q = sTick[sj];
        if (q >= (unsigned)ntiles) break;
        const int sn = (i + 1) & 3;
        const unsigned qn = sTick[sn];

        // (a) convert NEXT tile into the other XB (overlaps mma below)
        if (qn < (unsigned)ntiles) {
            MBAR_WAIT(sb + OFF_MBAR + 8 * sn, (ph >> sn) & 1);
            ph ^= (1u << sn);
            convert(xs_a[sn], xb_a[(i + 1) & 1]);
        }

        // (b) mma from XB[i&1] (tile q, converted last iteration)
        const uint32_t xb = xb_a[i & 1];
        float acc[2][4][4];
        #pragma unroll
        for (int mt = 0; mt < 2; ++mt)
            #pragma unroll
            for (int nt = 0; nt < 4; ++nt)
                #pragma unroll
                for (int qq = 0; qq < 4; ++qq) acc[mt][nt][qq] = 0.f;

        #pragma unroll
        for (int ks = 0; ks < 8; ++ks) {
            uint32_t a[2][4];
            const uint32_t chunk = (uint32_t)(2 * ks + khalf);
            const uint32_t csw = (chunk ^ lr7) << 4;
            #pragma unroll
            for (int mt = 0; mt < 2; ++mt) {
                const uint32_t addr =
                    xb + (uint32_t)(wm * 32 + mt * 16 + rsub) * 256 + csw;
                asm volatile("ldmatrix.sync.aligned.m8n8.x4.shared.b16 {%0,%1,%2,%3}, [%4];"
                             : "=r"(a[mt][0]), "=r"(a[mt][1]), "=r"(a[mt][2]), "=r"(a[mt][3])
                             : "r"(addr));
            }
            #pragma unroll
            for (int mt = 0; mt < 2; ++mt)
                #pragma unroll
                for (int nt = 0; nt < 4; ++nt) {
                    asm volatile(
                        "mma.sync.aligned.m16n8k16.row.col.f32.bf16.bf16.f32 "
                        "{%0,%1,%2,%3}, {%4,%5,%6,%7}, {%8,%9}, {%0,%1,%2,%3};"
                        : "+f"(acc[mt][nt][0]), "+f"(acc[mt][nt][1]),
                          "+f"(acc[mt][nt][2]), "+f"(acc[mt][nt][3])
                        : "r"(a[mt][0]), "r"(a[mt][1]), "r"(a[mt][2]), "r"(a[mt][3]),
                          "r"(breg[nt][ks][0]), "r"(breg[nt][ks][1]));
                }
        }

        // (c) epilogue: Y = X + acc + c, in place in XS[sj]
        {
            const uint32_t xsn = xs_a[sj] + (uint32_t)wn * 8192;
            #pragma unroll
            for (int mt = 0; mt < 2; ++mt) {
                const uint32_t rA = (uint32_t)(wm * 32 + mt * 16) + (uint32_t)(lane >> 2);
                const uint32_t baseA = xsn + rA * 128;
                const uint32_t baseB = xsn + (rA + 8) * 128;
                #pragma unroll
                for (int nt = 0; nt < 4; ++nt) {
                    const uint32_t q16 = (uint32_t)(nt * 2) + eq16b;
                    const uint32_t aA = baseA + ((q16 ^ er7a) << 4) + einner;
                    const uint32_t aB = baseB + ((q16 ^ er7a) << 4) + einner;
                    float f0, f1;
                    asm volatile("ld.shared.v2.f32 {%0,%1}, [%2];"
                                 : "=f"(f0), "=f"(f1) : "r"(aA));
                    f0 += acc[mt][nt][0] + cv[nt][0];
                    f1 += acc[mt][nt][1] + cv[nt][1];
                    asm volatile("st.shared.v2.f32 [%0], {%1,%2};"
                                 :: "r"(aA), "f"(f0), "f"(f1) : "memory");
                    asm volatile("ld.shared.v2.f32 {%0,%1}, [%2];"
                                 : "=f"(f0), "=f"(f1) : "r"(aB));
                    f0 += acc[mt][nt][2] + cv[nt][0];
                    f1 += acc[mt][nt][3] + cv[nt][1];
                    asm volatile("st.shared.v2.f32 [%0], {%1,%2};"
                                 :: "r"(aB), "f"(f0), "f"(f1) : "memory");
                }
            }
        }
        FENCE_ASYNC();
        __syncthreads();   // XB[(i+1)&1] ready; epilogue done in XS[sj]

        // (d) tid0: deferred reload, store tile q, new ticket
        if (tid == 0) {
            if (pend_stage >= 0) {
                asm volatile("cp.async.bulk.wait_group.read 0;" ::: "memory");
                if (pend_tick < (unsigned)ntiles) {
                    MBAR_EXPECT(sb + OFF_MBAR + 8 * pend_stage, TILE_BYTES);
                    #pragma unroll
                    for (int ac = 0; ac < 4; ++ac)
                        TMA_LOAD2D(xs_a[pend_stage] + ac * 8192, &tmX,
                                   ac * 32, (int)pend_tick * BM,
                                   sb + OFF_MBAR + 8 * pend_stage);
                }
            }
            #pragma unroll
            for (int ac = 0; ac < 4; ++ac)
                TMA_STORE2D(&tmY, ac * 32, (int)q * BM, xs_a[sj] + ac * 8192);
            asm volatile("cp.async.bulk.commit_group;" ::: "memory");
            const unsigned nn = atomicAdd(&g_tile_ctr, 1u);
            sTick[sj] = nn;
        }
        pend_stage = sj;
        if (tid == 0) pend_tick = sTick[sj];
    }

    if (tid == 0)
        asm volatile("cp.async.bulk.wait_group 0;" ::: "memory");
}

// ================= host ====================================================
typedef CUresult (*PFN_encodeTiled)(
    CUtensorMap*, CUtensorMapDataType, cuuint32_t, void*,
    const cuuint64_t*, const cuuint64_t*, const cuuint32_t*, const cuuint32_t*,
    CUtensorMapInterleave, CUtensorMapSwizzle, CUtensorMapL2promotion,
    CUtensorMapFloatOOBfill);

extern "C" void kernel_launch(void* const* d_in, const int* in_sizes, int n_in,
                              void* d_out, int out_size)
{
    const float* X    = (const float*)d_in[0];
    const float* Wv   = (const float*)d_in[7];
    const float* bv   = (const float*)d_in[8];
    const float* W_in = (const float*)d_in[9];
    const float* b_in = (const float*)d_in[10];
    const float* W_mo = (const float*)d_in[11];
    const float* b_mo = (const float*)d_in[12];
    const float* Wo   = (const float*)d_in[13];
    const float* bo   = (const float*)d_in[14];
    float* Y = (float*)d_out;

    const int E = in_sizes[0] / HID;
    const int ntiles = (E + BM - 1) / BM;

    cudaFuncSetAttribute(prep, cudaFuncAttributeMaxDynamicSharedMemorySize, 131072);
    prep<<<64, 256, 131072>>>(Wo, W_mo, W_in, Wv, bv, b_in, b_mo, bo);

    void* pfn = nullptr;
    cudaDriverEntryPointQueryResult qr;
    cudaGetDriverEntryPoint("cuTensorMapEncodeTiled", &pfn, cudaEnableDefault, &qr);
    PFN_encodeTiled encode = (PFN_encodeTiled)pfn;

    CUtensorMap tmX, tmY;
    cuuint64_t dims[2] = { (cuuint64_t)HID, (cuuint64_t)E };
    cuuint64_t str[1]  = { (cuuint64_t)HID * 4 };
    cuuint32_t box[2]  = { 32, 64 };
    cuuint32_t es[2]   = { 1, 1 };
    encode(&tmX, CU_TENSOR_MAP_DATA_TYPE_FLOAT32, 2, (void*)X,
           dims, str, box, es, CU_TENSOR_MAP_INTERLEAVE_NONE,
           CU_TENSOR_MAP_SWIZZLE_128B, CU_TENSOR_MAP_L2_PROMOTION_L2_128B,
           CU_TENSOR_MAP_FLOAT_OOB_FILL_NONE);
    encode(&tmY, CU_TENSOR_MAP_DATA_TYPE_FLOAT32, 2, (void*)Y,
           dims, str, box, es, CU_TENSOR_MAP_INTERLEAVE_NONE,
           CU_TENSOR_MAP_SWIZZLE_128B, CU_TENSOR_MAP_L2_PROMOTION_L2_128B,
           CU_TENSOR_MAP_FLOAT_OOB_FILL_NONE);

    cudaFuncSetAttribute(fused_main, cudaFuncAttributeMaxDynamicSharedMemorySize, SMEM_TOTAL);
    fused_main<<<GRID, NTHREADS, SMEM_TOTAL>>>(tmX, tmY, ntiles);
}

// round 13
// speedup vs baseline: 1.2808x; 1.1660x over previous
#include <cuda_runtime.h>
#include <cuda.h>
#include <cuda_bf16.h>
#include <cstdint>
#include <cstddef>

#define HID 128
#define BM 64
#define TILE_BYTES 32768
#define GRID_MAIN 296          // 2 CTAs per SM
#define NTHREADS 128

// ---------------- device scratch ----------------
__device__ float g_B[HID * HID];                 // Wiv @ Wv
__device__ float g_u[HID];
__device__ __nv_bfloat16 g_Bf[16 * 8 * 2 * 32 * 2]; // 0.5*M^T bf16, fragment layout
__device__ float g_c[HID];
__device__ unsigned int g_tile_ctr;
__device__ unsigned int g_sync;                  // epoch barrier (monotonic)

__device__ __forceinline__ uint32_t smem_u32(const void* p) {
    uint32_t a;
    asm("{ .reg .u64 t; cvta.to.shared.u64 t, %1; cvt.u32.u64 %0, t; }" : "=r"(a) : "l"(p));
    return a;
}
__device__ __forceinline__ float warp_red(float p) {
    p += __shfl_xor_sync(0xffffffffu, p, 16);
    p += __shfl_xor_sync(0xffffffffu, p, 8);
    p += __shfl_xor_sync(0xffffffffu, p, 4);
    p += __shfl_xor_sync(0xffffffffu, p, 2);
    p += __shfl_xor_sync(0xffffffffu, p, 1);
    return p;
}
__device__ __forceinline__ uint32_t packbf(float lo, float hi) {
    uint32_t d;
    asm("cvt.rn.bf16x2.f32 %0, %1, %2;" : "=r"(d) : "f"(hi), "f"(lo));
    return d;
}
#define CPA16(dst, src) \
    asm volatile("cp.async.cg.shared.global [%0], [%1], 16;" :: "r"(dst), "l"(src))
#define CPA_WAIT_ALL() \
    asm volatile("cp.async.commit_group;\ncp.async.wait_group 0;" ::: "memory")

// ================= prep (single kernel, 64 blocks x 2 rows) ===============
// (verbatim from R12 — proven correct, ~6.5us)
__global__ __launch_bounds__(256) void prep(
    const float* __restrict__ Wo, const float* __restrict__ W_mo,
    const float* __restrict__ W_in, const float* __restrict__ Wv,
    const float* __restrict__ bv, const float* __restrict__ b_in,
    const float* __restrict__ b_mo, const float* __restrict__ bo)
{
    extern __shared__ float sm[];          // sW[16384] | sV[16384]
    float* sW = sm;
    float* sV = sm + 16384;
    __shared__ float sWo[2][HID], sWiv[2][HID], sAsh[2][HID], sw_own[2];

    const int b = blockIdx.x, t = threadIdx.x;
    const int r0 = b * 2;
    if (b == 0 && t == 0) g_tile_ctr = 0;

    const uint32_t sWa  = smem_u32(sW);
    const uint32_t sVa  = smem_u32(sV);
    const uint32_t sWoA = smem_u32(&sWo[0][0]);
    const uint32_t sWiA = smem_u32(&sWiv[0][0]);
    if (t < 64) {
        CPA16(sWoA + t * 16, Wo + r0 * HID + t * 4);
    } else if (t < 128) {
        const int i = t - 64;
        CPA16(sWiA + i * 16, W_in + (256 + r0) * HID + i * 4);
    }
    #pragma unroll
    for (int q = 0; q < 16; ++q) {
        const int i = q * 256 + t;
        CPA16(sWa + i * 16, W_mo + i * 4);
        CPA16(sVa + i * 16, Wv + i * 4);
    }
    CPA_WAIT_ALL();
    __syncthreads();

    const int wid = t >> 5, lane = t & 31;
    if (t < HID) {
        float a0 = 0.f, a1 = 0.f;
        #pragma unroll
        for (int j = 0; j < HID; ++j) {
            const float m = sW[j * HID + t];
            a0 += sWo[0][j] * m;
            a1 += sWo[1][j] * m;
        }
        sAsh[0][t] = a0;
        sAsh[1][t] = a1;
    } else {
        const int c = t - HID;
        float a0 = 0.f, a1 = 0.f;
        #pragma unroll
        for (int j = 0; j < HID; ++j) {
            const float m = sV[j * HID + c];
            a0 += sWiv[0][j] * m;
            a1 += sWiv[1][j] * m;
        }
        g_B[(r0 + 0) * HID + c] = a0;
        g_B[(r0 + 1) * HID + c] = a1;
    }
    if (wid < 2) {
        float p = 0.f;
        #pragma unroll
        for (int j = lane; j < HID; j += 32) p += sWiv[wid][j] * bv[j];
        p = warp_red(p);
        if (lane == 0) g_u[r0 + wid] = p + b_in[256 + r0 + wid];
    } else if (wid < 4) {
        const int rr = wid - 2;
        float p = 0.f;
        #pragma unroll
        for (int j = lane; j < HID; j += 32) p += sWo[rr][j] * b_mo[j];
        p = warp_red(p);
        if (lane == 0) sw_own[rr] = p + bo[r0 + rr];
    }
    __threadfence();
    __syncthreads();

    if (t == 0) {
        const unsigned v = atomicAdd(&g_sync, 1u);
        const unsigned target = ((v >> 6) + 1u) << 6;
        unsigned cur;
        do {
            asm volatile("ld.volatile.global.u32 %0, [%1];" : "=r"(cur) : "l"(&g_sync));
        } while (cur < target);
    }
    __syncthreads();

    #pragma unroll
    for (int q = 0; q < 16; ++q) {
        const int i = q * 256 + t;
        CPA16(sWa + i * 16, g_B + i * 4);
    }
    CPA_WAIT_ALL();
    __syncthreads();

    if (t < HID) {
        float m0 = 0.f, m1 = 0.f;
        #pragma unroll
        for (int j = 0; j < HID; ++j) {
            const float v = sW[j * HID + t];
            m0 += sAsh[0][j] * v;
            m1 += sAsh[1][j] * v;
        }
        const int i = t;
        const int ks = i >> 4, r = i & 15;
        const int regi = (r >> 3) & 1, half = r & 1;
        #pragma unroll
        for (int rr = 0; rr < 2; ++rr) {
            const int o = r0 + rr;
            const int nt = o >> 3;
            const int lane2 = ((o & 7) << 2) | ((r & 7) >> 1);
            const int idx = ((((nt * 8 + ks) * 2 + regi) * 32) + lane2) * 2 + half;
            g_Bf[idx] = __float2bfloat16(0.5f * (rr ? m1 : m0));
        }
    }
    if (wid < 2) {
        float p = 0.f;
        #pragma unroll
        for (int j = lane; j < HID; j += 32) p += sAsh[wid][j] * g_u[j];
        p = warp_red(p);
        if (lane == 0) g_c[r0 + wid] = 0.5f * (p + sw_own[wid]);
    }
}

// ================= main: 2 CTAs/SM x 128 threads =====================
// per-CTA smem: XS0..2 @0/32768/65536 (32KB fp32 SW128), XB @98304 (16KB),
//               mbar[3] @114688, sTick[3] @114712; total 114752
#define OFF_XB   98304u
#define OFF_MBAR 114688u
#define OFF_TICK 114712u
#define SMEM_TOTAL 114752

#define MBAR_INIT(a, c) \
    asm volatile("mbarrier.init.shared.b64 [%0], %1;" :: "r"(a), "r"(c) : "memory")
#define MBAR_EXPECT(a, b) \
    asm volatile("mbarrier.arrive.expect_tx.shared.b64 _, [%0], %1;" :: "r"(a), "r"(b) : "memory")
#define MBAR_WAIT(mbar, par) do {                                             \
    uint32_t _m = (mbar); uint32_t _p = (par); uint32_t _d;                   \
    asm volatile("{\n\t.reg .pred p;\n\t"                                     \
        "mbarrier.try_wait.parity.acquire.cta.shared::cta.b64 p, [%1], %2;\n\t" \
        "selp.b32 %0, 1, 0, p;\n\t}"                                          \
        : "=r"(_d) : "r"(_m), "r"(_p) : "memory");                            \
    if (!_d) {                                                                \
        asm volatile("{\n\t.reg .pred P1;\n\t"                                \
            "W_%=:\n\t"                                                       \
            "mbarrier.try_wait.parity.acquire.cta.shared::cta.b64 P1, [%0], %1, 0x989680;\n\t" \
            "@P1 bra.uni D_%=;\n\t"                                           \
            "bra.uni W_%=;\n\t"                                               \
            "D_%=:\n\t}" :: "r"(_m), "r"(_p) : "memory");                     \
    }                                                                         \
} while (0)

#define TMA_LOAD2D(dst, map, x, y, mb) \
    asm volatile("cp.async.bulk.tensor.2d.shared::cta.global.tile.mbarrier::complete_tx::bytes " \
                 "[%0], [%1, {%2, %3}], [%4];" \
                 :: "r"(dst), "l"(map), "r"(x), "r"(y), "r"(mb) : "memory")
#define TMA_STORE2D(map, x, y, src) \
    asm volatile("cp.async.bulk.tensor.2d.global.shared::cta.tile.bulk_group " \
                 "[%0, {%1, %2}], [%3];" \
                 :: "l"(map), "r"(x), "r"(y), "r"(src) : "memory")
#define FENCE_ASYNC() asm volatile("fence.proxy.async.shared::cta;" ::: "memory")

__global__ __launch_bounds__(NTHREADS, 2) void fused_main(
    const __grid_constant__ CUtensorMap tmX,
    const __grid_constant__ CUtensorMap tmY,
    int ntiles)
{
    extern __shared__ __align__(1024) unsigned char smem_raw[];
    const uint32_t sb = smem_u32(smem_raw);
    const int tid  = threadIdx.x;
    const int lane = tid & 31;
    const int wn = tid >> 5;                 // 1(m) x 4(n) warp grid
    const uint32_t xs_a[3] = { sb, sb + 32768u, sb + 65536u };
    const uint32_t xb = sb + OFF_XB;
    unsigned* sTick = reinterpret_cast<unsigned*>(smem_raw + OFF_TICK);

    // ---- B fragments in registers ----
    uint32_t breg[4][8][2];
    {
        const uint32_t* bp = reinterpret_cast<const uint32_t*>(g_Bf);
        #pragma unroll
        for (int nt = 0; nt < 4; ++nt)
            #pragma unroll
            for (int ks = 0; ks < 8; ++ks)
                #pragma unroll
                for (int ri = 0; ri < 2; ++ri)
                    breg[nt][ks][ri] =
                        bp[(((wn * 4 + nt) * 8 + ks) * 2 + ri) * 32 + lane];
    }
    float cv[4][2];
    #pragma unroll
    for (int nt = 0; nt < 4; ++nt) {
        const int col = wn * 32 + nt * 8 + 2 * (lane & 3);
        cv[nt][0] = g_c[col];
        cv[nt][1] = g_c[col + 1];
    }

    if (tid == 0) {
        #pragma unroll
        for (int st = 0; st < 3; ++st) MBAR_INIT(sb + OFF_MBAR + 8 * st, 1);
    }
    __syncthreads();

    // prologue: 3 tickets, 3 loads
    if (tid == 0) {
        #pragma unroll
        for (int st = 0; st < 3; ++st) {
            const unsigned c = atomicAdd(&g_tile_ctr, 1u);
            sTick[st] = c;
            if (c < (unsigned)ntiles) {
                MBAR_EXPECT(sb + OFF_MBAR + 8 * st, TILE_BYTES);
                #pragma unroll
                for (int ac = 0; ac < 4; ++ac)
                    TMA_LOAD2D(xs_a[st] + ac * 8192, &tmX, ac * 32, (int)c * BM,
                               sb + OFF_MBAR + 8 * st);
            }
        }
    }
    __syncthreads();

    // per-thread constants
    const int crow = tid >> 1, ch = tid & 1;   // convert: 64 rows x 2 threads
    const uint32_t cr7 = (uint32_t)(crow & 7);
    const int rsub = lane & 15;
    const uint32_t lr7 = (uint32_t)(rsub & 7);
    const int khalf = lane >> 4;
    const uint32_t er7a = (uint32_t)(lane >> 2);
    const uint32_t einner = (uint32_t)(lane & 1) * 8;
    const uint32_t eq16b = (uint32_t)((lane & 3) >> 1);

    unsigned ph = 0;
    int pend_stage = -1;
    unsigned pend_tick = 0;

    for (int i = 0; ; ++i) {
        const int p = i % 3;
        const unsigned q = sTick[p];
        if (q >= (unsigned)ntiles) break;

        MBAR_WAIT(sb + OFF_MBAR + 8 * p, (ph >> p) & 1);
        ph ^= (1u << p);

        // ---- convert fp32 XS[p] -> bf16 XB ----
        {
            const uint32_t rxs = xs_a[p] + (uint32_t)crow * 128;
            const uint32_t rxb = xb + (uint32_t)crow * 256;
            #pragma unroll
            for (int j = 0; j < 8; ++j) {
                const int cj = ch * 8 + j;
                const uint32_t c32 = (uint32_t)(cj >> 2) * 8192;
                const uint32_t q0 = (uint32_t)((cj & 3) * 2);
                const uint32_t a0 = rxs + c32 + ((q0 ^ cr7) << 4);
                const uint32_t a1 = rxs + c32 + (((q0 + 1) ^ cr7) << 4);
                float x0, x1, x2, x3, y0, y1, y2, y3;
                asm volatile("ld.shared.v4.f32 {%0,%1,%2,%3}, [%4];"
                             : "=f"(x0), "=f"(x1), "=f"(x2), "=f"(x3) : "r"(a0));
                asm volatile("ld.shared.v4.f32 {%0,%1,%2,%3}, [%4];"
                             : "=f"(y0), "=f"(y1), "=f"(y2), "=f"(y3) : "r"(a1));
                const uint32_t p0 = packbf(x0, x1), p1 = packbf(x2, x3);
                const uint32_t p2 = packbf(y0, y1), p3 = packbf(y2, y3);
                const uint32_t ab = rxb + (((uint32_t)cj ^ cr7) << 4);
                asm volatile("st.shared.v4.b32 [%0], {%1,%2,%3,%4};"
                             :: "r"(ab), "r"(p0), "r"(p1), "r"(p2), "r"(p3) : "memory");
            }
        }
        __syncthreads();   // XB ready

        // ---- mma from XB: warp tile m64 x n32 ----
        float acc[4][4][4];
        #pragma unroll
        for (int mt = 0; mt < 4; ++mt)
            #pragma unroll
            for (int nt = 0; nt < 4; ++nt)
                #pragma unroll
                for (int qq = 0; qq < 4; ++qq) acc[mt][nt][qq] = 0.f;

        #pragma unroll
        for (int ks = 0; ks < 8; ++ks) {
            uint32_t a[4][4];
            const uint32_t chunk = (uint32_t)(2 * ks + khalf);
            const uint32_t csw = (chunk ^ lr7) << 4;
            #pragma unroll
            for (int mt = 0; mt < 4; ++mt) {
                const uint32_t addr =
                    xb + (uint32_t)(mt * 16 + rsub) * 256 + csw;
                asm volatile("ldmatrix.sync.aligned.m8n8.x4.shared.b16 {%0,%1,%2,%3}, [%4];"
                             : "=r"(a[mt][0]), "=r"(a[mt][1]), "=r"(a[mt][2]), "=r"(a[mt][3])
                             : "r"(addr));
            }
            #pragma unroll
            for (int mt = 0; mt < 4; ++mt)
                #pragma unroll
                for (int nt = 0; nt < 4; ++nt) {
                    asm volatile(
                        "mma.sync.aligned.m16n8k16.row.col.f32.bf16.bf16.f32 "
                        "{%0,%1,%2,%3}, {%4,%5,%6,%7}, {%8,%9}, {%0,%1,%2,%3};"
                        : "+f"(acc[mt][nt][0]), "+f"(acc[mt][nt][1]),
                          "+f"(acc[mt][nt][2]), "+f"(acc[mt][nt][3])
                        : "r"(a[mt][0]), "r"(a[mt][1]), "r"(a[mt][2]), "r"(a[mt][3]),
                          "r"(breg[nt][ks][0]), "r"(breg[nt][ks][1]));
                }
        }

        // ---- epilogue: Y = X + acc + c, in place in XS[p] ----
        {
            const uint32_t xsn = xs_a[p] + (uint32_t)wn * 8192;
            #pragma unroll
            for (int mt = 0; mt < 4; ++mt) {
                const uint32_t rA = (uint32_t)(mt * 16) + (uint32_t)(lane >> 2);
                const uint32_t baseA = xsn + rA * 128;
                const uint32_t baseB = xsn + (rA + 8) * 128;
                #pragma unroll
                for (int nt = 0; nt < 4; ++nt) {
                    const uint32_t q16 = (uint32_t)(nt * 2) + eq16b;
                    const uint32_t aA = baseA + ((q16 ^ er7a) << 4) + einner;
                    const uint32_t aB = baseB + ((q16 ^ (er7a + 8u & 7u)) << 4);  // placeholder (fixed below)
                    (void)aB;
                    float f0, f1;
                    asm volatile("ld.shared.v2.f32 {%0,%1}, [%2];"
                                 : "=f"(f0), "=f"(f1) : "r"(aA));
                    f0 += acc[mt][nt][0] + cv[nt][0];
                    f1 += acc[mt][nt][1] + cv[nt][1];
                    asm volatile("st.shared.v2.f32 [%0], {%1,%2};"
                                 :: "r"(aA), "f"(f0), "f"(f1) : "memory");
                    const uint32_t aB2 = baseB + ((q16 ^ er7a) << 4) + einner;
                    asm volatile("ld.shared.v2.f32 {%0,%1}, [%2];"
                                 : "=f"(f0), "=f"(f1) : "r"(aB2));
                    f0 += acc[mt][nt][2] + cv[nt][0];
                    f1 += acc[mt][nt][3] + cv[nt][1];
                    asm volatile("st.shared.v2.f32 [%0], {%1,%2};"
                                 :: "r"(aB2), "f"(f0), "f"(f1) : "memory");
                }
            }
        }
        FENCE_ASYNC();
        __syncthreads();

        // ---- tid0: deferred reload, store tile q, new ticket ----
        if (tid == 0) {
            if (pend_stage >= 0) {
                asm volatile("cp.async.bulk.wait_group.read 0;" ::: "memory");
                if (pend_tick < (unsigned)ntiles) {
                    MBAR_EXPECT(sb + OFF_MBAR + 8 * pend_stage, TILE_BYTES);
                    #pragma unroll
                    for (int ac = 0; ac < 4; ++ac)
                        TMA_LOAD2D(xs_a[pend_stage] + ac * 8192, &tmX,
                                   ac * 32, (int)pend_tick * BM,
                                   sb + OFF_MBAR + 8 * pend_stage);
                }
            }
            #pragma unroll
            for (int ac = 0; ac < 4; ++ac)
                TMA_STORE2D(&tmY, ac * 32, (int)q * BM, xs_a[p] + ac * 8192);
            asm volatile("cp.async.bulk.commit_group;" ::: "memory");
            const unsigned nn = atomicAdd(&g_tile_ctr, 1u);
            sTick[p] = nn;
            pend_tick = nn;
        }
        pend_stage = p;
    }

    if (tid == 0)
        asm volatile("cp.async.bulk.wait_group 0;" ::: "memory");
}

// ================= host ====================================================
typedef CUresult (*PFN_encodeTiled)(
    CUtensorMap*, CUtensorMapDataType, cuuint32_t, void*,
    const cuuint64_t*, const cuuint64_t*, const cuuint32_t*, const cuuint32_t*,
    CUtensorMapInterleave, CUtensorMapSwizzle, CUtensorMapL2promotion,
    CUtensorMapFloatOOBfill);

extern "C" void kernel_launch(void* const* d_in, const int* in_sizes, int n_in,
                              void* d_out, int out_size)
{
    const float* X    = (const float*)d_in[0];
    const float* Wv   = (const float*)d_in[7];
    const float* bv   = (const float*)d_in[8];
    const float* W_in = (const float*)d_in[9];
    const float* b_in = (const float*)d_in[10];
    const float* W_mo = (const float*)d_in[11];
    const float* b_mo = (const float*)d_in[12];
    const float* Wo   = (const float*)d_in[13];
    const float* bo   = (const float*)d_in[14];
    float* Y = (float*)d_out;

    const int E = in_sizes[0] / HID;
    const int ntiles = (E + BM - 1) / BM;

    cudaFuncSetAttribute(prep, cudaFuncAttributeMaxDynamicSharedMemorySize, 131072);
    prep<<<64, 256, 131072>>>(Wo, W_mo, W_in, Wv, bv, b_in, b_mo, bo);

    void* pfn = nullptr;
    cudaDriverEntryPointQueryResult qr;
    cudaGetDriverEntryPoint("cuTensorMapEncodeTiled", &pfn, cudaEnableDefault, &qr);
    PFN_encodeTiled encode = (PFN_encodeTiled)pfn;

    CUtensorMap tmX, tmY;
    cuuint64_t dims[2] = { (cuuint64_t)HID, (cuuint64_t)E };
    cuuint64_t str[1]  = { (cuuint64_t)HID * 4 };
    cuuint32_t box[2]  = { 32, 64 };
    cuuint32_t es[2]   = { 1, 1 };
    encode(&tmX, CU_TENSOR_MAP_DATA_TYPE_FLOAT32, 2, (void*)X,
           dims, str, box, es, CU_TENSOR_MAP_INTERLEAVE_NONE,
           CU_TENSOR_MAP_SWIZZLE_128B, CU_TENSOR_MAP_L2_PROMOTION_L2_128B,
           CU_TENSOR_MAP_FLOAT_OOB_FILL_NONE);
    encode(&tmY, CU_TENSOR_MAP_DATA_TYPE_FLOAT32, 2, (void*)Y,
           dims, str, box, es, CU_TENSOR_MAP_INTERLEAVE_NONE,
           CU_TENSOR_MAP_SWIZZLE_128B, CU_TENSOR_MAP_L2_PROMOTION_L2_128B,
           CU_TENSOR_MAP_FLOAT_OOB_FILL_NONE);

    cudaFuncSetAttribute(fused_main, cudaFuncAttributeMaxDynamicSharedMemorySize, SMEM_TOTAL);
    fused_main<<<GRID_MAIN, NTHREADS, SMEM_TOTAL>>>(tmX, tmY, ntiles);
}